// round 2
// baseline (speedup 1.0000x reference)
#include <cuda_runtime.h>
#include <cuda_bf16.h>

// -------- constants from the reference --------
#define POOL_SIZE   32
#define PROMPT_LEN  32
#define NCTX        32
#define EMBED       768
#define TOP_K       5
#define N_CLS       1000
#define SUFFIX_LEN  12
#define EMBED_F4    (EMBED / 4)          // 192
#define ROW_TOTAL   (1 + PROMPT_LEN + NCTX + SUFFIX_LEN)   // 77
#define CLS_F4      (ROW_TOTAL * EMBED_F4)                  // 14784
#define PROMPTS_F4  ((unsigned)N_CLS * CLS_F4)              // 14,784,000
#define POOL_F4     (POOL_SIZE * PROMPT_LEN * EMBED_F4)     // 196,608
#define KEY_F4      (POOL_SIZE * EMBED_F4)                  // 6,144

// -------- device scratch (no allocations allowed) --------
__device__ float4 g_combined4[PROMPT_LEN * EMBED_F4];

// ============================================================
// Fused kernel: selection + gating + combined, ONE block, 1024 thr
// ============================================================
__global__ __launch_bounds__(1024, 1)
void kAB_fused(const float4* __restrict__ x4,       // [16,192]
               const float4* __restrict__ key4,     // [32,192]
               const float4* __restrict__ pool4,    // [32,32,192]
               const float4* __restrict__ aw4,      // [192]
               const float*  __restrict__ ab)       // [1]
{
    __shared__ float4 part[4][EMBED_F4];   // 12 KB partial q sums
    __shared__ float4 qs4[EMBED_F4];       // 3 KB
    __shared__ float4 aw_s[EMBED_F4];      // 3 KB
    __shared__ float  sim[POOL_SIZE];
    __shared__ int    idxs[TOP_K];

    const int t = threadIdx.x;
    const int w = t >> 5, lane = t & 31;

    // ---- phase 1a: partial q sums, 768 threads / 24 warps, 4 frames each
    if (t < 768) {
        const int grp = t / EMBED_F4;       // 0..3
        const int col = t - grp * EMBED_F4;
        float4 s = make_float4(0.f, 0.f, 0.f, 0.f);
        #pragma unroll
        for (int f = 0; f < 4; ++f) {
            float4 v = x4[(grp * 4 + f) * EMBED_F4 + col];
            s.x += v.x; s.y += v.y; s.z += v.z; s.w += v.w;
        }
        part[grp][col] = s;
    } else if (t < 768 + EMBED_F4) {
        aw_s[t - 768] = aw4[t - 768];       // stage alpha_w
    }
    __syncthreads();
    if (t < EMBED_F4) {
        float4 a = part[0][t], b = part[1][t], c = part[2][t], d = part[3][t];
        qs4[t] = make_float4(a.x+b.x+c.x+d.x, a.y+b.y+c.y+d.y,
                             a.z+b.z+c.z+d.z, a.w+b.w+c.w+d.w);
    }
    __syncthreads();

    // ---- phase 1b: one warp per pool key: sim = (k.q)/||k||
    {
        const float4* kp = key4 + w * EMBED_F4;
        float dot = 0.f, nrm = 0.f;
        #pragma unroll
        for (int i = 0; i < 6; ++i) {
            const int c = lane + i * 32;
            float4 kv = kp[c], qv = qs4[c];
            dot += kv.x*qv.x + kv.y*qv.y + kv.z*qv.z + kv.w*qv.w;
            nrm += kv.x*kv.x + kv.y*kv.y + kv.z*kv.z + kv.w*kv.w;
        }
        #pragma unroll
        for (int o = 16; o; o >>= 1) {
            dot += __shfl_down_sync(0xffffffffu, dot, o);
            nrm += __shfl_down_sync(0xffffffffu, nrm, o);
        }
        if (lane == 0) sim[w] = dot * rsqrtf(nrm);
    }
    __syncthreads();

    // ---- phase 1c: top-5, strict '>' = lowest index wins ties (jax.lax.top_k)
    if (t == 0) {
        unsigned usedmask = 0u;
        for (int k = 0; k < TOP_K; ++k) {
            int best = 0; float bv = -3.0e38f;
            #pragma unroll
            for (int p = 0; p < POOL_SIZE; ++p)
                if (!((usedmask >> p) & 1u) && sim[p] > bv) { bv = sim[p]; best = p; }
            usedmask |= 1u << best;
            idxs[k] = best;
        }
    }
    __syncthreads();

    // ---- phase 2: one warp per token position l = w (32 warps = 32 pos)
    const float ab0 = ab[0];
    const float4* rows[TOP_K];
    #pragma unroll
    for (int k = 0; k < TOP_K; ++k)
        rows[k] = pool4 + (idxs[k] * PROMPT_LEN + w) * EMBED_F4;

    float dots[TOP_K] = {0.f, 0.f, 0.f, 0.f, 0.f};
    #pragma unroll
    for (int i = 0; i < 6; ++i) {
        const int c = lane + i * 32;
        float4 av = aw_s[c];
        #pragma unroll
        for (int k = 0; k < TOP_K; ++k) {
            float4 rv = rows[k][c];
            dots[k] += rv.x*av.x + rv.y*av.y + rv.z*av.z + rv.w*av.w;
        }
    }
    #pragma unroll
    for (int k = 0; k < TOP_K; ++k) {
        #pragma unroll
        for (int o = 16; o; o >>= 1)
            dots[k] += __shfl_xor_sync(0xffffffffu, dots[k], o);  // all lanes get it
    }
    float wt[TOP_K];
    #pragma unroll
    for (int k = 0; k < TOP_K; ++k)
        wt[k] = 1.f / (1.f + __expf(-(dots[k] + ab0)));

    #pragma unroll
    for (int i = 0; i < 6; ++i) {
        const int c = lane + i * 32;
        float4 acc = make_float4(0.f, 0.f, 0.f, 0.f);
        #pragma unroll
        for (int k = 0; k < TOP_K; ++k) {
            float4 rv = rows[k][c];               // L1 hit (just read above)
            acc.x += wt[k]*rv.x; acc.y += wt[k]*rv.y;
            acc.z += wt[k]*rv.z; acc.w += wt[k]*rv.w;
        }
        g_combined4[w * EMBED_F4 + c] = acc;
    }
}

// ============================================================
// Kernel C: the bandwidth kernel — build prompts + copy pool/key.
// Flat float4 grid-stride. 32-bit indexing (total < 2^31).
// ============================================================
__global__ void kC_emit(const float4* __restrict__ pre4,
                        const float4* __restrict__ suf4,
                        const float4* __restrict__ ctx4,
                        const float4* __restrict__ pol4,
                        const float4* __restrict__ key4,
                        float4* __restrict__ out,
                        unsigned total_f4)
{
    const float4* __restrict__ cmb4 = g_combined4;

    unsigned idx = blockIdx.x * blockDim.x + threadIdx.x;
    const unsigned stride = gridDim.x * blockDim.x;

    for (; idx < total_f4; idx += stride) {
        float4 v;
        if (idx < PROMPTS_F4) {
            unsigned c   = idx / CLS_F4;              // magic-multiply
            unsigned fc  = idx - c * CLS_F4;
            unsigned row = fc / EMBED_F4;
            unsigned col = fc - row * EMBED_F4;
            if (row == 0)
                v = __ldcs(&pre4[c * EMBED_F4 + col]);            // read-once
            else if (row <= PROMPT_LEN)
                v = __ldg(&cmb4[(row - 1) * EMBED_F4 + col]);     // hot, keep cached
            else if (row <= PROMPT_LEN + NCTX)
                v = __ldg(&ctx4[(row - 1 - PROMPT_LEN) * EMBED_F4 + col]);
            else
                v = __ldcs(&suf4[c * (SUFFIX_LEN * EMBED_F4)
                          + (row - 1 - PROMPT_LEN - NCTX) * EMBED_F4 + col]);
        } else {
            unsigned r = idx - PROMPTS_F4;
            v = (r < POOL_F4) ? __ldcs(&pol4[r]) : __ldcs(&key4[r - POOL_F4]);
        }
        __stcs(&out[idx], v);   // streaming store: output never re-read
    }
}

// ============================================================
extern "C" void kernel_launch(void* const* d_in, const int* in_sizes, int n_in,
                              void* d_out, int out_size)
{
    const float* x_embed      = (const float*)d_in[0];
    const float* prompt_pool  = (const float*)d_in[1];
    const float* prompt_key   = (const float*)d_in[2];
    const float* alpha_w      = (const float*)d_in[3];
    const float* alpha_b      = (const float*)d_in[4];
    const float* ctx          = (const float*)d_in[5];
    const float* token_prefix = (const float*)d_in[6];
    const float* token_suffix = (const float*)d_in[7];
    // d_in[8] = train_flag: the penalty is a positive scalar on sims ->
    // top-k ordering (and therefore the output) is unchanged; safely ignored.

    kAB_fused<<<1, 1024>>>((const float4*)x_embed, (const float4*)prompt_key,
                           (const float4*)prompt_pool, (const float4*)alpha_w,
                           alpha_b);

    const unsigned total_f4 = (unsigned)(out_size / 4);
    const int threads = 256;
    unsigned want = (total_f4 + 7u) / 8u;                 // ~8 f4 per thread
    unsigned blocks = (want + threads - 1) / threads;
    if (blocks > 65535u) blocks = 65535u;
    if (blocks < 1u) blocks = 1u;
    kC_emit<<<blocks, threads>>>((const float4*)token_prefix,
                                 (const float4*)token_suffix,
                                 (const float4*)ctx,
                                 (const float4*)prompt_pool,
                                 (const float4*)prompt_key,
                                 (float4*)d_out, total_f4);
}

// round 3
// speedup vs baseline: 1.1832x; 1.1832x over previous
#include <cuda_runtime.h>
#include <cuda_bf16.h>

// -------- constants from the reference --------
#define POOL_SIZE   32
#define PROMPT_LEN  32
#define NCTX        32
#define EMBED       768
#define TOP_K       5
#define N_CLS       1000
#define SUFFIX_LEN  12
#define EMBED_F4    (EMBED / 4)          // 192
#define ROW_TOTAL   (1 + PROMPT_LEN + NCTX + SUFFIX_LEN)   // 77
#define CLS_F4      14784u               // 77*192
#define PROMPTS_F4  14784000u            // 1000*14784
#define POOL_F4     196608u              // 32*32*192
#define SUF_F4      2304u                // 12*192

// Row-granular work decomposition (each "row" = 192 float4 = one warp-iter):
//   Phase A (independent of selection): 1000*45 prompt rows (prefix/ctx/suffix)
//                                       + 1056 pool/key rows  => 46,056 rows
//   Phase B (depends on combined):      1000*32 rows          => 32,000 rows
#define NROWS_A     46056u
#define NROWS_B     32000u
#define GRID_X      152

// -------- device scratch / sync state (zero-init at load) --------
__device__ float4 g_combined4[PROMPT_LEN * EMBED_F4];
__device__ int      g_flag;
__device__ unsigned g_done;

// ============================================================
// Block 0's work: selection + gating + combined (1024 threads)
// ============================================================
__device__ __forceinline__
void compute_combined(const float4* __restrict__ x4,
                      const float4* __restrict__ key4,
                      const float4* __restrict__ pool4,
                      const float4* __restrict__ aw4,
                      const float*  __restrict__ ab,
                      float4 (&part)[4][EMBED_F4],
                      float4 (&qs4)[EMBED_F4],
                      float4 (&aw_s)[EMBED_F4],
                      float  (&sim)[POOL_SIZE],
                      int    (&idxs)[TOP_K])
{
    const int t = threadIdx.x;
    const int w = t >> 5, lane = t & 31;

    // ---- partial q sums (mean scale & q-norm don't affect top-k ordering)
    if (t < 768) {
        const int grp = t / EMBED_F4;       // 0..3
        const int col = t - grp * EMBED_F4;
        float4 s = make_float4(0.f, 0.f, 0.f, 0.f);
        #pragma unroll
        for (int f = 0; f < 4; ++f) {
            float4 v = x4[(grp * 4 + f) * EMBED_F4 + col];
            s.x += v.x; s.y += v.y; s.z += v.z; s.w += v.w;
        }
        part[grp][col] = s;
    } else if (t < 768 + EMBED_F4) {
        aw_s[t - 768] = aw4[t - 768];       // stage alpha_w
    }
    __syncthreads();
    if (t < EMBED_F4) {
        float4 a = part[0][t], b = part[1][t], c = part[2][t], d = part[3][t];
        qs4[t] = make_float4(a.x+b.x+c.x+d.x, a.y+b.y+c.y+d.y,
                             a.z+b.z+c.z+d.z, a.w+b.w+c.w+d.w);
    }
    __syncthreads();

    // ---- one warp per pool key: sim = (k.q)/||k||  (cosine-order equivalent)
    {
        const float4* kp = key4 + w * EMBED_F4;
        float dot = 0.f, nrm = 0.f;
        #pragma unroll
        for (int i = 0; i < 6; ++i) {
            const int c = lane + i * 32;
            float4 kv = kp[c], qv = qs4[c];
            dot += kv.x*qv.x + kv.y*qv.y + kv.z*qv.z + kv.w*qv.w;
            nrm += kv.x*kv.x + kv.y*kv.y + kv.z*kv.z + kv.w*kv.w;
        }
        #pragma unroll
        for (int o = 16; o; o >>= 1) {
            dot += __shfl_down_sync(0xffffffffu, dot, o);
            nrm += __shfl_down_sync(0xffffffffu, nrm, o);
        }
        if (lane == 0) sim[w] = dot * rsqrtf(nrm);
    }
    __syncthreads();

    // ---- top-5, strict '>' = lowest index wins ties (matches jax.lax.top_k)
    if (t == 0) {
        unsigned usedmask = 0u;
        for (int k = 0; k < TOP_K; ++k) {
            int best = 0; float bv = -3.0e38f;
            #pragma unroll
            for (int p = 0; p < POOL_SIZE; ++p)
                if (!((usedmask >> p) & 1u) && sim[p] > bv) { bv = sim[p]; best = p; }
            usedmask |= 1u << best;
            idxs[k] = best;
        }
    }
    __syncthreads();

    // ---- one warp per token position l = w: gates + weighted sum
    const float ab0 = ab[0];
    const float4* rows[TOP_K];
    #pragma unroll
    for (int k = 0; k < TOP_K; ++k)
        rows[k] = pool4 + (idxs[k] * PROMPT_LEN + w) * EMBED_F4;

    float dots[TOP_K] = {0.f, 0.f, 0.f, 0.f, 0.f};
    #pragma unroll
    for (int i = 0; i < 6; ++i) {
        const int c = lane + i * 32;
        float4 av = aw_s[c];
        #pragma unroll
        for (int k = 0; k < TOP_K; ++k) {
            float4 rv = rows[k][c];
            dots[k] += rv.x*av.x + rv.y*av.y + rv.z*av.z + rv.w*av.w;
        }
    }
    #pragma unroll
    for (int k = 0; k < TOP_K; ++k) {
        #pragma unroll
        for (int o = 16; o; o >>= 1)
            dots[k] += __shfl_xor_sync(0xffffffffu, dots[k], o);
    }
    float wt[TOP_K];
    #pragma unroll
    for (int k = 0; k < TOP_K; ++k)
        wt[k] = 1.f / (1.f + __expf(-(dots[k] + ab0)));

    #pragma unroll
    for (int i = 0; i < 6; ++i) {
        const int c = lane + i * 32;
        float4 acc = make_float4(0.f, 0.f, 0.f, 0.f);
        #pragma unroll
        for (int k = 0; k < TOP_K; ++k) {
            float4 rv = rows[k][c];               // L1 hit
            acc.x += wt[k]*rv.x; acc.y += wt[k]*rv.y;
            acc.z += wt[k]*rv.z; acc.w += wt[k]*rv.w;
        }
        g_combined4[w * EMBED_F4 + c] = acc;
    }
}

// Row copy helpers: 192 float4 per warp => 6 per lane (MLP=6, fully coalesced)
__device__ __forceinline__
void copy_row_stream(const float4* __restrict__ src, float4* __restrict__ dst, int lane)
{
    float4 v[6];
    #pragma unroll
    for (int i = 0; i < 6; ++i) v[i] = __ldcs(&src[lane + i * 32]);
    #pragma unroll
    for (int i = 0; i < 6; ++i) __stcs(&dst[lane + i * 32], v[i]);
}
__device__ __forceinline__
void copy_row_cached(const float4* __restrict__ src, float4* __restrict__ dst, int lane)
{
    float4 v[6];
    #pragma unroll
    for (int i = 0; i < 6; ++i) v[i] = __ldg(&src[lane + i * 32]);
    #pragma unroll
    for (int i = 0; i < 6; ++i) __stcs(&dst[lane + i * 32], v[i]);
}

// ============================================================
// The single persistent kernel
// ============================================================
__global__ __launch_bounds__(1024, 1)
void k_all(const float4* __restrict__ x4,
           const float4* __restrict__ key4,
           const float4* __restrict__ pool4,
           const float4* __restrict__ aw4,
           const float*  __restrict__ ab,
           const float4* __restrict__ pre4,
           const float4* __restrict__ suf4,
           const float4* __restrict__ ctx4,
           float4* __restrict__ out)
{
    __shared__ float4 part[4][EMBED_F4];
    __shared__ float4 qs4[EMBED_F4];
    __shared__ float4 aw_s[EMBED_F4];
    __shared__ float  sim[POOL_SIZE];
    __shared__ int    idxs[TOP_K];

    const int t = threadIdx.x;
    const int w = t >> 5, lane = t & 31;
    const unsigned b = blockIdx.x;
    const unsigned nb = gridDim.x;

    if (b == 0) {
        // ---- selection + gating + combined, then release the flag
        compute_combined(x4, key4, pool4, aw4, ab, part, qs4, aw_s, sim, idxs);
        __syncthreads();
        __threadfence();
        if (t == 0) atomicExch(&g_flag, 1);
    } else {
        // ---- Phase A: all output regions independent of 'combined'
        const unsigned WA = (nb - 1u) * 32u;
        const unsigned wA = (b - 1u) * 32u + (unsigned)w;
        for (unsigned R = wA; R < NROWS_A; R += WA) {
            if (R < 45000u) {
                const unsigned c = R / 45u;
                const unsigned r = R - c * 45u;
                if (r == 0u) {
                    copy_row_stream(pre4 + c * EMBED_F4,
                                    out + c * CLS_F4, lane);
                } else if (r <= 32u) {
                    // ctx row (re-read 1000x -> keep cached)
                    copy_row_cached(ctx4 + (r - 1u) * EMBED_F4,
                                    out + c * CLS_F4 + (r + 32u) * EMBED_F4, lane);
                } else {
                    copy_row_stream(suf4 + c * SUF_F4 + (r - 33u) * EMBED_F4,
                                    out + c * CLS_F4 + (r + 32u) * EMBED_F4, lane);
                }
            } else {
                const unsigned q = R - 45000u;       // 0..1055: pool then key
                const float4* src = (q < 1024u) ? (pool4 + q * EMBED_F4)
                                                : (key4 + (q - 1024u) * EMBED_F4);
                copy_row_stream(src, out + PROMPTS_F4 + q * EMBED_F4, lane);
            }
        }
        // ---- wait for combined
        if (t == 0) {
            while (atomicAdd(&g_flag, 0) == 0) __nanosleep(128);
        }
        __syncthreads();
        __threadfence();
    }

    // ---- Phase B: combined rows (source is L2/L1 hot)
    {
        const unsigned WB = nb * 32u;
        const unsigned wB = b * 32u + (unsigned)w;
        const float4* __restrict__ cmb4 = g_combined4;
        for (unsigned R = wB; R < NROWS_B; R += WB) {
            const unsigned c = R >> 5;
            const unsigned r = R & 31u;
            copy_row_cached(cmb4 + r * EMBED_F4,
                            out + c * CLS_F4 + (r + 1u) * EMBED_F4, lane);
        }
    }

    // ---- self-reset sync state so every graph replay starts clean
    __syncthreads();
    if (t == 0) {
        __threadfence();
        unsigned prev = atomicAdd(&g_done, 1u);
        if (prev == nb - 1u) { g_done = 0u; g_flag = 0; }
    }
}

// ============================================================
extern "C" void kernel_launch(void* const* d_in, const int* in_sizes, int n_in,
                              void* d_out, int out_size)
{
    const float* x_embed      = (const float*)d_in[0];
    const float* prompt_pool  = (const float*)d_in[1];
    const float* prompt_key   = (const float*)d_in[2];
    const float* alpha_w      = (const float*)d_in[3];
    const float* alpha_b      = (const float*)d_in[4];
    const float* ctx          = (const float*)d_in[5];
    const float* token_prefix = (const float*)d_in[6];
    const float* token_suffix = (const float*)d_in[7];
    // d_in[8] = train_flag: the penalty is a positive scalar on sims ->
    // top-k ordering (and therefore the output) is unchanged; safely ignored.

    k_all<<<GRID_X, 1024>>>((const float4*)x_embed,
                            (const float4*)prompt_key,
                            (const float4*)prompt_pool,
                            (const float4*)alpha_w,
                            alpha_b,
                            (const float4*)token_prefix,
                            (const float4*)token_suffix,
                            (const float4*)ctx,
                            (float4*)d_out);
}